// round 1
// baseline (speedup 1.0000x reference)
#include <cuda_runtime.h>
#include <cuda_bf16.h>

// Problem constants (GNHP_32796370273029)
#define BB      128      // batch
#define TP2     2050     // T+2
#define TS      2049     // scan steps
#define HH      64       // hidden
#define GG      448      // 7*H gates
#define KK      100      // num event types (output)
#define NE      103      // K+3 embedding rows

typedef unsigned long long ull;

// ---------------- packed f32x2 helpers ----------------
__device__ __forceinline__ ull pack2(float lo, float hi) {
    ull r; asm("mov.b64 %0, {%1, %2};" : "=l"(r) : "f"(lo), "f"(hi)); return r;
}
__device__ __forceinline__ void unpack2(ull v, float& lo, float& hi) {
    asm("mov.b64 {%0, %1}, %2;" : "=f"(lo), "=f"(hi) : "l"(v));
}
__device__ __forceinline__ void fma2(ull& d, ull a, ull b) {
    asm("fma.rn.f32x2 %0, %1, %2, %0;" : "+l"(d) : "l"(a), "l"(b));
}

// ---------------- fast transcendentals (fp32, ~2ulp — fine for 1e-3) ----------------
__device__ __forceinline__ float sigm_f(float x) {
    return __fdividef(1.0f, 1.0f + __expf(-x));
}
__device__ __forceinline__ float tanh_f(float x) {
    float e = __expf(2.0f * x);
    return 1.0f - __fdividef(2.0f, e + 1.0f);
}
__device__ __forceinline__ float softplus_f(float x) {
    return fmaxf(x, 0.0f) + __logf(1.0f + __expf(-fabsf(x)));
}

// ---------------- scratch (device globals — no allocs allowed) ----------------
__device__ float g_P[NE * GG];                 // precomputed in_emb@Wx + b   (184 KB)
__device__ ull   g_OET[32 * 128];              // out_emb transposed, packed pairs, padded (32 KB)
__device__ float g_HS[(long)BB * TS * HH];     // hidden states (67 MB)

// ============================================================
// Kernel 1: precompute P = in_emb @ Wx + b   and packed/transposed out_emb
// grid: 104 blocks x 448 threads. Blocks 0..102 -> P rows; block 103 -> OET.
// ============================================================
__global__ void prep_kernel(const float* __restrict__ in_emb,
                            const float* __restrict__ Wx,
                            const float* __restrict__ bias,
                            const float* __restrict__ out_emb) {
    int j = threadIdx.x;
    if (blockIdx.x < NE) {
        int e = blockIdx.x;
        __shared__ float emb_s[HH];
        if (j < HH) emb_s[j] = in_emb[e * HH + j];
        __syncthreads();
        float acc = bias[j];
        #pragma unroll
        for (int k = 0; k < HH; k++)
            acc = fmaf(emb_s[k], Wx[k * GG + j], acc);
        g_P[e * GG + j] = acc;
    } else {
        // OET[p][c] = (out_emb[c][2p], out_emb[c][2p+1]), padded to 128 cols with zeros
        for (int i = j; i < 32 * 128; i += GG) {
            int p = i >> 7, c = i & 127;
            ull v = 0ULL;
            if (c < KK) v = pack2(out_emb[c * HH + 2 * p], out_emb[c * HH + 2 * p + 1]);
            g_OET[i] = v;
        }
    }
}

// ============================================================
// Kernel 2: sequential CT-LSTM scan. One CTA per batch row, 448 threads
// (thread j owns gate j; its Wh column pairs live in registers).
// ============================================================
__global__ __launch_bounds__(GG, 1)
void scan_kernel(const int* __restrict__ ev,
                 const float* __restrict__ dts,
                 const float* __restrict__ Wh) {
    const int b = blockIdx.x;
    const int j = threadIdx.x;

    __shared__ __align__(16) float h_sm[HH];
    __shared__ float tg_sm[GG];
    __shared__ int   ev_sm[TS];
    __shared__ float dt_sm[TS];

    // preload this row's events and dts (one-time)
    for (int t = j; t < TS; t += GG) {
        ev_sm[t] = ev[b * TP2 + t];          // event_tensor[:, :-1]
        dt_sm[t] = dts[b * TP2 + t + 1];     // dtime_tensor[:, 1:]
    }
    if (j < HH) h_sm[j] = 0.0f;

    // pack Wh column j, k-pairs, into registers: wh[k] = (Wh[2k][j], Wh[2k+1][j])
    ull wh[32];
    #pragma unroll
    for (int k = 0; k < 32; k++) {
        float w0 = Wh[(2 * k) * GG + j];
        float w1 = Wh[(2 * k + 1) * GG + j];
        wh[k] = pack2(w0, w1);
    }

    float c_reg = 0.0f, cb_reg = 0.0f;   // state (meaningful for j < 64)
    const int type = j >> 6;             // 0:i 1:f 2:z 3:o 4:ib 5:fb 6:delta
    const int d    = j & 63;

    __syncthreads();

    float p_cur = g_P[ev_sm[0] * GG + j];

    for (int t = 0; t < TS; t++) {
        // prefetch next step's pre-activation while we compute the dot
        int e_next = (t + 1 < TS) ? ev_sm[t + 1] : 0;
        float p_next = g_P[e_next * GG + j];

        // g_j = p_cur + h . Wh[:, j]   via packed f32x2, 2 accumulator chains
        ull a0 = pack2(p_cur, 0.0f);
        ull a1 = pack2(0.0f, 0.0f);
        const ull* hp = reinterpret_cast<const ull*>(h_sm);
        #pragma unroll
        for (int k = 0; k < 32; k += 2) {
            fma2(a0, hp[k],     wh[k]);
            fma2(a1, hp[k + 1], wh[k + 1]);
        }
        float l0, h0, l1, h1;
        unpack2(a0, l0, h0);
        unpack2(a1, l1, h1);
        float g = (l0 + h0) + (l1 + h1);

        // per-gate nonlinearity (warp-uniform: type constant within each warp)
        float tg;
        if (type == 2)      tg = tanh_f(g);
        else if (type == 6) tg = softplus_f(g);
        else                tg = sigm_f(g);
        tg_sm[j] = tg;
        __syncthreads();   // gates ready

        if (j < HH) {
            float i_  = tg_sm[d];
            float f_  = tg_sm[64  + d];
            float z_  = tg_sm[128 + d];
            float o_  = tg_sm[192 + d];
            float ib_ = tg_sm[256 + d];
            float fb_ = tg_sm[320 + d];
            float dl_ = tg_sm[384 + d];
            float c_i  = fmaf(f_,  c_reg,  i_  * z_);
            float cb_i = fmaf(fb_, cb_reg, ib_ * z_);
            float edec = __expf(-dl_ * dt_sm[t]);
            float c_n  = cb_i + (c_i - cb_i) * edec;
            float h    = o_ * tanh_f(c_n);
            c_reg  = c_n;
            cb_reg = cb_i;
            h_sm[d] = h;
            g_HS[((long)b * TS + t) * HH + d] = h;
        }
        __syncthreads();   // h ready for next step
        p_cur = p_next;
    }
}

// ============================================================
// Kernel 3: out = softplus(hs @ out_emb^T)
// 128 threads (4 warps). CTA covers 64 rows (8 chunks of 8).
// Warp w handles 2 rows per chunk; lane l handles cols {l, 32+l, 64+l, 96+l}.
// ============================================================
__global__ __launch_bounds__(128, 6)
void logits_kernel(float* __restrict__ out) {
    __shared__ ull oe[32 * 128];                    // [p][c] padded (32 KB)
    __shared__ __align__(16) float h8[8 * HH];      // 8 rows of h (2 KB)

    const int tid  = threadIdx.x;
    const int warp = tid >> 5;
    const int lane = tid & 31;

    for (int i = tid; i < 32 * 128; i += 128) oe[i] = g_OET[i];

    const long rowbase = (long)blockIdx.x * 64;

    for (int sub = 0; sub < 8; sub++) {
        const long r0 = rowbase + sub * 8;
        __syncthreads();
        // coop load 8 rows (512 floats = 128 float4, coalesced)
        const float4* src = reinterpret_cast<const float4*>(g_HS + r0 * HH);
        reinterpret_cast<float4*>(h8)[tid] = src[tid];
        __syncthreads();

        const ull* hr0 = reinterpret_cast<const ull*>(h8 + (warp * 2) * HH);
        const ull* hr1 = hr0 + 32;

        ull acc[2][4];
        #pragma unroll
        for (int r = 0; r < 2; r++)
            #pragma unroll
            for (int m = 0; m < 4; m++)
                acc[r][m] = 0ULL;

        #pragma unroll
        for (int p = 0; p < 32; p++) {
            ull hp0 = hr0[p];
            ull hp1 = hr1[p];
            #pragma unroll
            for (int m = 0; m < 4; m++) {
                ull w = oe[p * 128 + m * 32 + lane];   // conflict-free, zero-padded
                fma2(acc[0][m], hp0, w);
                fma2(acc[1][m], hp1, w);
            }
        }

        #pragma unroll
        for (int r = 0; r < 2; r++) {
            long row = r0 + warp * 2 + r;
            #pragma unroll
            for (int m = 0; m < 4; m++) {
                int c = m * 32 + lane;
                if (c < KK) {
                    float lo, hi;
                    unpack2(acc[r][m], lo, hi);
                    out[row * KK + c] = softplus_f(lo + hi);
                }
            }
        }
    }
}

// ============================================================
extern "C" void kernel_launch(void* const* d_in, const int* in_sizes, int n_in,
                              void* d_out, int out_size) {
    const int*   ev      = (const int*)  d_in[0];   // event_tensor (B, 2050) int32
    const float* dts     = (const float*)d_in[1];   // dtime_tensor (B, 2050)
    const float* in_emb  = (const float*)d_in[2];   // (103, 64)
    const float* Wx      = (const float*)d_in[3];   // (64, 448)
    const float* Wh      = (const float*)d_in[4];   // (64, 448)
    const float* bias    = (const float*)d_in[5];   // (448,)
    const float* out_emb = (const float*)d_in[6];   // (100, 64)
    float* out = (float*)d_out;                     // (128, 2049, 100)

    prep_kernel<<<NE + 1, GG>>>(in_emb, Wx, bias, out_emb);
    scan_kernel<<<BB, GG>>>(ev, dts, Wh);
    logits_kernel<<<(BB * TS) / 64, 128>>>(out);
}

// round 6
// speedup vs baseline: 1.1524x; 1.1524x over previous
#include <cuda_runtime.h>
#include <cuda_bf16.h>

// Problem constants (GNHP_32796370273029)
#define BB      128      // batch
#define TP2     2050     // T+2
#define TS      2049     // scan steps
#define HH      64       // hidden
#define GG      448      // 7*H gates
#define KK      100      // num event types (output)
#define NE      103      // K+3 embedding rows
#define NT      224      // scan threads (2 gates per thread)

typedef unsigned long long ull;

// ---------------- packed f32x2 helpers ----------------
__device__ __forceinline__ ull pack2(float lo, float hi) {
    ull r; asm("mov.b64 %0, {%1, %2};" : "=l"(r) : "f"(lo), "f"(hi)); return r;
}
__device__ __forceinline__ void unpack2(ull v, float& lo, float& hi) {
    asm("mov.b64 {%0, %1}, %2;" : "=f"(lo), "=f"(hi) : "l"(v));
}
__device__ __forceinline__ void fma2(ull& d, ull a, ull b) {
    asm("fma.rn.f32x2 %0, %1, %2, %0;" : "+l"(d) : "l"(a), "l"(b));
}

// ---------------- raw MUFU wrappers ----------------
__device__ __forceinline__ float ex2f(float x) {
    float r; asm("ex2.approx.f32 %0, %1;" : "=f"(r) : "f"(x)); return r;
}
__device__ __forceinline__ float rcpf(float x) {
    float r; asm("rcp.approx.f32 %0, %1;" : "=f"(r) : "f"(x)); return r;
}
__device__ __forceinline__ float lg2f(float x) {
    float r; asm("lg2.approx.f32 %0, %1;" : "=f"(r) : "f"(x)); return r;
}

#define L2E 1.4426950408889634f
#define LN2 0.6931471805599453f

// Unified gate nonlinearity. type: 0,1,3,4,5=sigmoid  2=tanh  6=softplus.
// Branchless except the (warp-uniform) softplus arm.
__device__ __forceinline__ float act(float g, int type) {
    float a = (type == 2) ? (2.0f * L2E) : ((type == 6) ? L2E : -L2E);
    float t = ex2f(g * a);            // e^{2g} | e^{g} | e^{-g}
    float u = 1.0f + t;
    float r = rcpf(u);
    float res = (type == 2) ? fmaf(-2.0f, r, 1.0f) : r;
    if (type == 6) {                  // warp-uniform (gates 384..447)
        float sp = lg2f(u) * LN2;
        res = (g > 80.0f) ? g : sp;
    }
    return res;
}

__device__ __forceinline__ float softplus_f(float x) {
    return fmaxf(x, 0.0f) + __logf(1.0f + __expf(-fabsf(x)));
}

// ---------------- scratch (device globals — no allocs allowed) ----------------
__device__ float g_P[NE * GG];                 // precomputed in_emb@Wx + b
__device__ ull   g_OET[32 * 128];              // out_emb transposed, packed pairs
__device__ float g_HS[(long)BB * TS * HH];     // hidden states (67 MB)

// ============================================================
// Kernel 1: precompute P = in_emb @ Wx + b  and packed/transposed out_emb
// ============================================================
__global__ void prep_kernel(const float* __restrict__ in_emb,
                            const float* __restrict__ Wx,
                            const float* __restrict__ bias,
                            const float* __restrict__ out_emb) {
    int j = threadIdx.x;
    if (blockIdx.x < NE) {
        int e = blockIdx.x;
        __shared__ float emb_s[HH];
        if (j < HH) emb_s[j] = in_emb[e * HH + j];
        __syncthreads();
        float acc = bias[j];
        #pragma unroll
        for (int k = 0; k < HH; k++)
            acc = fmaf(emb_s[k], Wx[k * GG + j], acc);
        g_P[e * GG + j] = acc;
    } else {
        for (int i = j; i < 32 * 128; i += GG) {
            int p = i >> 7, c = i & 127;
            ull v = 0ULL;
            if (c < KK) v = pack2(out_emb[c * HH + 2 * p], out_emb[c * HH + 2 * p + 1]);
            g_OET[i] = v;
        }
    }
}

// ============================================================
// Kernel 2: sequential CT-LSTM scan. One CTA per batch row, 224 threads.
// Thread j owns gates j and j+224; both Wh column-pair sets live in regs.
// State update only in warps 0-1 (j<64: warp-uniform branch for warps 2-6).
// ============================================================
__global__ __launch_bounds__(NT, 1)
void scan_kernel(const int* __restrict__ ev,
                 const float* __restrict__ dts,
                 const float* __restrict__ Wh) {
    const int b = blockIdx.x;
    const int j = threadIdx.x;

    __shared__ __align__(16) float h_sm[HH];
    __shared__ float tg_sm[GG];
    __shared__ int   ev_sm[TS];
    __shared__ float ndt_sm[TS];      // -log2(e) * dt  (pre-scaled for ex2)

    for (int t = j; t < TS; t += NT) {
        ev_sm[t]  = ev[b * TP2 + t];             // event_tensor[:, :-1]
        ndt_sm[t] = -L2E * dts[b * TP2 + t + 1]; // dtime_tensor[:, 1:]
    }
    if (j < HH) h_sm[j] = 0.0f;

    // Wh column pairs for both gate slots, in registers.
    ull wa[32], wb[32];
    #pragma unroll
    for (int k = 0; k < 32; k++) {
        wa[k] = pack2(Wh[(2 * k) * GG + j],        Wh[(2 * k + 1) * GG + j]);
        wb[k] = pack2(Wh[(2 * k) * GG + j + NT],   Wh[(2 * k + 1) * GG + j + NT]);
    }

    const int ta = j >> 6;            // type of gate slot A (warp-uniform)
    const int tb = (j + NT) >> 6;     // type of gate slot B (warp-uniform)
    const int d  = j & 63;

    float c_reg = 0.0f, cb_reg = 0.0f;

    __syncthreads();

    float pa = g_P[ev_sm[0] * GG + j];
    float pb = g_P[ev_sm[0] * GG + j + NT];

    for (int t = 0; t < TS; t++) {
        // prefetch next step's pre-activations
        int e_next = (t + 1 < TS) ? ev_sm[t + 1] : 0;
        float pa_n = g_P[e_next * GG + j];
        float pb_n = g_P[e_next * GG + j + NT];

        // two 64-dots, 8 accumulator chains (depth 8), shared h loads
        ull a0 = pack2(pa, 0.0f), a1 = 0ULL, a2 = 0ULL, a3 = 0ULL;
        ull b0 = pack2(pb, 0.0f), b1 = 0ULL, b2 = 0ULL, b3 = 0ULL;
        const ull* hp = reinterpret_cast<const ull*>(h_sm);
        #pragma unroll
        for (int k = 0; k < 32; k += 4) {
            ull h0 = hp[k], h1 = hp[k + 1], h2 = hp[k + 2], h3 = hp[k + 3];
            fma2(a0, h0, wa[k]);     fma2(b0, h0, wb[k]);
            fma2(a1, h1, wa[k + 1]); fma2(b1, h1, wb[k + 1]);
            fma2(a2, h2, wa[k + 2]); fma2(b2, h2, wb[k + 2]);
            fma2(a3, h3, wa[k + 3]); fma2(b3, h3, wb[k + 3]);
        }
        float ga, gb;
        { float u0,u1,u2,u3,u4,u5,u6,u7;
          unpack2(a0,u0,u1); unpack2(a1,u2,u3); unpack2(a2,u4,u5); unpack2(a3,u6,u7);
          ga = ((u0+u1)+(u2+u3)) + ((u4+u5)+(u6+u7)); }
        { float u0,u1,u2,u3,u4,u5,u6,u7;
          unpack2(b0,u0,u1); unpack2(b1,u2,u3); unpack2(b2,u4,u5); unpack2(b3,u6,u7);
          gb = ((u0+u1)+(u2+u3)) + ((u4+u5)+(u6+u7)); }

        tg_sm[j]      = act(ga, ta);
        tg_sm[j + NT] = act(gb, tb);
        __syncthreads();              // gates ready; h_sm reads done

        // state update: warps 0-1 only (warp-uniform branch for warps 2-6)
        if (j < HH) {
            float i_  = tg_sm[d];
            float f_  = tg_sm[64  + d];
            float z_  = tg_sm[128 + d];
            float o_  = tg_sm[192 + d];
            float ib_ = tg_sm[256 + d];
            float fb_ = tg_sm[320 + d];
            float dl_ = tg_sm[384 + d];
            float c_i  = fmaf(f_,  c_reg,  i_  * z_);
            float cb_i = fmaf(fb_, cb_reg, ib_ * z_);
            float edec = ex2f(dl_ * ndt_sm[t]);          // e^{-delta*dt}
            float c_n  = fmaf(c_i - cb_i, edec, cb_i);
            // tanh(c_n) = 1 - 2/(1+e^{2c})
            float tt = ex2f(c_n * (2.0f * L2E));
            float th = fmaf(-2.0f, rcpf(1.0f + tt), 1.0f);
            float h  = o_ * th;
            c_reg  = c_n;
            cb_reg = cb_i;
            h_sm[d] = h;
            g_HS[((long)b * TS + t) * HH + d] = h;
        }
        __syncthreads();              // h ready for next step
        pa = pa_n; pb = pb_n;
    }
}

// ============================================================
// Padding no-op so ncu -s 5 -c 1 lands on a scan_kernel replay.
// ============================================================
__global__ void ncu_pad_kernel() {}

// ============================================================
// Kernel 3: out = softplus(hs @ out_emb^T)
// ============================================================
__global__ __launch_bounds__(128, 6)
void logits_kernel(float* __restrict__ out) {
    __shared__ ull oe[32 * 128];
    __shared__ __align__(16) float h8[8 * HH];

    const int tid  = threadIdx.x;
    const int warp = tid >> 5;
    const int lane = tid & 31;

    for (int i = tid; i < 32 * 128; i += 128) oe[i] = g_OET[i];

    const long rowbase = (long)blockIdx.x * 64;

    for (int sub = 0; sub < 8; sub++) {
        const long r0 = rowbase + sub * 8;
        __syncthreads();
        const float4* src = reinterpret_cast<const float4*>(g_HS + r0 * HH);
        reinterpret_cast<float4*>(h8)[tid] = src[tid];
        __syncthreads();

        const ull* hr0 = reinterpret_cast<const ull*>(h8 + (warp * 2) * HH);
        const ull* hr1 = hr0 + 32;

        ull acc[2][4];
        #pragma unroll
        for (int r = 0; r < 2; r++)
            #pragma unroll
            for (int m = 0; m < 4; m++)
                acc[r][m] = 0ULL;

        #pragma unroll
        for (int p = 0; p < 32; p++) {
            ull hp0 = hr0[p];
            ull hp1 = hr1[p];
            #pragma unroll
            for (int m = 0; m < 4; m++) {
                ull w = oe[p * 128 + m * 32 + lane];
                fma2(acc[0][m], hp0, w);
                fma2(acc[1][m], hp1, w);
            }
        }

        #pragma unroll
        for (int r = 0; r < 2; r++) {
            long row = r0 + warp * 2 + r;
            #pragma unroll
            for (int m = 0; m < 4; m++) {
                int c = m * 32 + lane;
                if (c < KK) {
                    float lo, hi;
                    unpack2(acc[r][m], lo, hi);
                    out[row * KK + c] = softplus_f(lo + hi);
                }
            }
        }
    }
}

// ============================================================
extern "C" void kernel_launch(void* const* d_in, const int* in_sizes, int n_in,
                              void* d_out, int out_size) {
    const int*   ev      = (const int*)  d_in[0];
    const float* dts     = (const float*)d_in[1];
    const float* in_emb  = (const float*)d_in[2];
    const float* Wx      = (const float*)d_in[3];
    const float* Wh      = (const float*)d_in[4];
    const float* bias    = (const float*)d_in[5];
    const float* out_emb = (const float*)d_in[6];
    float* out = (float*)d_out;

    prep_kernel<<<NE + 1, GG>>>(in_emb, Wx, bias, out_emb);
    scan_kernel<<<BB, NT>>>(ev, dts, Wh);
    ncu_pad_kernel<<<1, 32>>>();
    logits_kernel<<<(BB * TS) / 64, 128>>>(out);
}